// round 7
// baseline (speedup 1.0000x reference)
#include <cuda_runtime.h>
#include <math.h>

// Problem constants
#define B_   8
#define LQ_  1024
#define S_   256
#define D_   1024
#define H_   16
#define HD_  64
#define MQ_  (B_*LQ_)   // 8192
#define MKV_ (B_*S_)    // 2048

// ---------------------------------------------------------------------------
// Scratch (static device globals — no allocation in kernel_launch)
// ---------------------------------------------------------------------------
__device__ float g_q  [MQ_  * D_];
__device__ float g_k  [MKV_ * D_];
__device__ float g_v  [MKV_ * D_];
__device__ float g_ctx[MQ_  * D_];
__device__ float g_att[MQ_  * D_];
__device__ float g_mid[MQ_  * D_];
__device__ float g_ffn[MQ_  * D_];

// ---------------------------------------------------------------------------
// SGEMM NT: C[M,N] = act(A[M,K] * B[N,K]^T + bias)
// A is split at column ksplit between A0 (lda0) and A1 (lda1) to fuse concat.
// BM=BN=128, BK=16, 256 threads, 8x8 microtile (2x2 raked 64-blocks).
// ---------------------------------------------------------------------------
__global__ __launch_bounds__(256, 2)
void sgemm_nt(int M, int N, int K,
              const float* __restrict__ A0, int lda0,
              const float* __restrict__ A1, int lda1, int ksplit,
              const float* __restrict__ Bm, int ldb,
              const float* __restrict__ bias,
              float* __restrict__ C, int ldc, int act)
{
    __shared__ float As[16 * 128];
    __shared__ float Bs[16 * 128];

    const int tid = threadIdx.x;
    const int tx  = tid & 15;   // col group
    const int ty  = tid >> 4;   // row group
    const int m0  = blockIdx.y * 128;
    const int n0  = blockIdx.x * 128;

    float acc[8][8];
#pragma unroll
    for (int i = 0; i < 8; i++)
#pragma unroll
        for (int j = 0; j < 8; j++) acc[i][j] = 0.f;

    for (int k0 = 0; k0 < K; k0 += 16) {
        // --- load A tile (128 rows x 16 k), transposed into As[k][row]
        const bool side0 = (k0 < ksplit);
#pragma unroll
        for (int it = 0; it < 2; it++) {
            int e   = tid + it * 256;
            int row = e >> 2;
            int c4  = e & 3;
            int gr  = m0 + row;
            const float* ap = side0 ? (A0 + (size_t)gr * lda0 + k0)
                                    : (A1 + (size_t)gr * lda1 + (k0 - ksplit));
            float4 v = *(const float4*)(ap + c4 * 4);
            As[(c4 * 4 + 0) * 128 + row] = v.x;
            As[(c4 * 4 + 1) * 128 + row] = v.y;
            As[(c4 * 4 + 2) * 128 + row] = v.z;
            As[(c4 * 4 + 3) * 128 + row] = v.w;
        }
        // --- load B tile (128 n-rows x 16 k), transposed into Bs[k][n]
#pragma unroll
        for (int it = 0; it < 2; it++) {
            int e   = tid + it * 256;
            int row = e >> 2;
            int c4  = e & 3;
            int gn  = n0 + row;
            float4 v = *(const float4*)(Bm + (size_t)gn * ldb + k0 + c4 * 4);
            Bs[(c4 * 4 + 0) * 128 + row] = v.x;
            Bs[(c4 * 4 + 1) * 128 + row] = v.y;
            Bs[(c4 * 4 + 2) * 128 + row] = v.z;
            Bs[(c4 * 4 + 3) * 128 + row] = v.w;
        }
        __syncthreads();

#pragma unroll
        for (int kk = 0; kk < 16; kk++) {
            float ra[8], rb[8];
#pragma unroll
            for (int i = 0; i < 4; i++) {
                ra[i]     = As[kk * 128 +       ty * 4 + i];
                ra[4 + i] = As[kk * 128 + 64 +  ty * 4 + i];
            }
            float4 b0 = *(const float4*)&Bs[kk * 128 +      tx * 4];
            float4 b1 = *(const float4*)&Bs[kk * 128 + 64 + tx * 4];
            rb[0] = b0.x; rb[1] = b0.y; rb[2] = b0.z; rb[3] = b0.w;
            rb[4] = b1.x; rb[5] = b1.y; rb[6] = b1.z; rb[7] = b1.w;
#pragma unroll
            for (int i = 0; i < 8; i++)
#pragma unroll
                for (int j = 0; j < 8; j++)
                    acc[i][j] = fmaf(ra[i], rb[j], acc[i][j]);
        }
        __syncthreads();
    }

    // --- epilogue: bias + optional relu, vectorized store
#pragma unroll
    for (int ri = 0; ri < 2; ri++) {
#pragma unroll
        for (int i = 0; i < 4; i++) {
            int gr = m0 + ri * 64 + ty * 4 + i;
#pragma unroll
            for (int rj = 0; rj < 2; rj++) {
                int gc = n0 + rj * 64 + tx * 4;
                float4 bv = *(const float4*)&bias[gc];
                float4 o;
                o.x = acc[ri * 4 + i][rj * 4 + 0] + bv.x;
                o.y = acc[ri * 4 + i][rj * 4 + 1] + bv.y;
                o.z = acc[ri * 4 + i][rj * 4 + 2] + bv.z;
                o.w = acc[ri * 4 + i][rj * 4 + 3] + bv.w;
                if (act == 1) {
                    o.x = fmaxf(o.x, 0.f); o.y = fmaxf(o.y, 0.f);
                    o.z = fmaxf(o.z, 0.f); o.w = fmaxf(o.w, 0.f);
                }
                *(float4*)&C[(size_t)gr * ldc + gc] = o;
            }
        }
    }
}

// ---------------------------------------------------------------------------
// Attention: per (b, h, 64-q-row tile).
//   P = softmax(Q K^T / 8), ctx = P V.  S=256 keys, HD=64, fully in smem.
// smem: QsT[64d][64r] | KsT[64d][256s] | Vs[256s][64d] | P[256s][65(r pad)]
// ---------------------------------------------------------------------------
#define ATT_SMEM_FLOATS (4096 + 16384 + 16384 + 16640)
#define ATT_SMEM_BYTES  (ATT_SMEM_FLOATS * 4)

__global__ __launch_bounds__(256, 1)
void attn_kernel(const float* __restrict__ q, const float* __restrict__ k,
                 const float* __restrict__ v, float* __restrict__ ctx)
{
    extern __shared__ float sm[];
    float* QsT = sm;               // [d][r]  64*64
    float* KsT = QsT + 4096;       // [d][s]  64*256
    float* Vs  = KsT + 16384;      // [s][d]  256*64
    float* P   = Vs  + 16384;      // [s][r]  256*65 (pad)

    const int tid = threadIdx.x;
    const int l0  = blockIdx.x * 64;
    const int h   = blockIdx.y;
    const int b   = blockIdx.z;

    const float* qb = q + ((size_t)(b * LQ_ + l0)) * D_ + h * HD_;
    const float* kb = k + ((size_t)(b * S_)) * D_ + h * HD_;
    const float* vb = v + ((size_t)(b * S_)) * D_ + h * HD_;

    // loads (float4, coalesced)
    for (int e = tid; e < 64 * 16; e += 256) {           // Q tile
        int r = e >> 4, d4 = e & 15;
        float4 vv = *(const float4*)(qb + (size_t)r * D_ + d4 * 4);
        QsT[(d4 * 4 + 0) * 64 + r] = vv.x;
        QsT[(d4 * 4 + 1) * 64 + r] = vv.y;
        QsT[(d4 * 4 + 2) * 64 + r] = vv.z;
        QsT[(d4 * 4 + 3) * 64 + r] = vv.w;
    }
    for (int e = tid; e < 256 * 16; e += 256) {          // K tile
        int s = e >> 4, d4 = e & 15;
        float4 vv = *(const float4*)(kb + (size_t)s * D_ + d4 * 4);
        KsT[(d4 * 4 + 0) * 256 + s] = vv.x;
        KsT[(d4 * 4 + 1) * 256 + s] = vv.y;
        KsT[(d4 * 4 + 2) * 256 + s] = vv.z;
        KsT[(d4 * 4 + 3) * 256 + s] = vv.w;
    }
    for (int e = tid; e < 256 * 16; e += 256) {          // V tile
        int s = e >> 4, d4 = e & 15;
        *(float4*)&Vs[s * 64 + d4 * 4] =
            *(const float4*)(vb + (size_t)s * D_ + d4 * 4);
    }
    __syncthreads();

    // phase A: P[s][r] = 0.125 * sum_d Q[r][d] K[s][d]   (64x256x64 GEMM)
    {
        const int tx = tid & 31;   // s groups
        const int ty = tid >> 5;   // r groups (0..7)
        float acc[8][8];
#pragma unroll
        for (int i = 0; i < 8; i++)
#pragma unroll
            for (int j = 0; j < 8; j++) acc[i][j] = 0.f;

#pragma unroll 4
        for (int d = 0; d < 64; d++) {
            float ra[8], rb[8];
#pragma unroll
            for (int i = 0; i < 4; i++) {
                ra[i]     = QsT[d * 64 +      ty * 4 + i];
                ra[4 + i] = QsT[d * 64 + 32 + ty * 4 + i];
            }
            float4 b0 = *(const float4*)&KsT[d * 256 +       tx * 4];
            float4 b1 = *(const float4*)&KsT[d * 256 + 128 + tx * 4];
            rb[0] = b0.x; rb[1] = b0.y; rb[2] = b0.z; rb[3] = b0.w;
            rb[4] = b1.x; rb[5] = b1.y; rb[6] = b1.z; rb[7] = b1.w;
#pragma unroll
            for (int i = 0; i < 8; i++)
#pragma unroll
                for (int j = 0; j < 8; j++)
                    acc[i][j] = fmaf(ra[i], rb[j], acc[i][j]);
        }
#pragma unroll
        for (int ri = 0; ri < 2; ri++)
#pragma unroll
            for (int i = 0; i < 4; i++)
#pragma unroll
                for (int rj = 0; rj < 2; rj++)
#pragma unroll
                    for (int j = 0; j < 4; j++) {
                        int r = ri * 32 + ty * 4 + i;
                        int s = rj * 128 + tx * 4 + j;
                        P[s * 65 + r] = acc[ri * 4 + i][rj * 4 + j] * 0.125f;
                    }
    }
    __syncthreads();

    // phase B: softmax over s for each of 64 rows (8 rows per warp)
    {
        const int lane = tid & 31, w = tid >> 5;
#pragma unroll
        for (int rr = 0; rr < 8; rr++) {
            int r = w * 8 + rr;
            float vals[8];
            float m = -1e30f;
#pragma unroll
            for (int qq = 0; qq < 8; qq++) {
                vals[qq] = P[(lane + qq * 32) * 65 + r];
                m = fmaxf(m, vals[qq]);
            }
#pragma unroll
            for (int off = 16; off; off >>= 1)
                m = fmaxf(m, __shfl_xor_sync(0xffffffffu, m, off));
            float sum = 0.f;
#pragma unroll
            for (int qq = 0; qq < 8; qq++) {
                vals[qq] = __expf(vals[qq] - m);
                sum += vals[qq];
            }
#pragma unroll
            for (int off = 16; off; off >>= 1)
                sum += __shfl_xor_sync(0xffffffffu, sum, off);
            float inv = 1.f / sum;
#pragma unroll
            for (int qq = 0; qq < 8; qq++)
                P[(lane + qq * 32) * 65 + r] = vals[qq] * inv;
        }
    }
    __syncthreads();

    // phase C: ctx[r][d] = sum_s P[s][r] V[s][d]   (64x64x256)
    {
        const int tx = tid & 15;   // d group
        const int ty = tid >> 4;   // r group
        float acc[4][4];
#pragma unroll
        for (int i = 0; i < 4; i++)
#pragma unroll
            for (int j = 0; j < 4; j++) acc[i][j] = 0.f;

#pragma unroll 8
        for (int s = 0; s < 256; s++) {
            float rp[4];
#pragma unroll
            for (int i = 0; i < 4; i++) rp[i] = P[s * 65 + ty * 4 + i];
            float4 vv = *(const float4*)&Vs[s * 64 + tx * 4];
#pragma unroll
            for (int i = 0; i < 4; i++) {
                acc[i][0] = fmaf(rp[i], vv.x, acc[i][0]);
                acc[i][1] = fmaf(rp[i], vv.y, acc[i][1]);
                acc[i][2] = fmaf(rp[i], vv.z, acc[i][2]);
                acc[i][3] = fmaf(rp[i], vv.w, acc[i][3]);
            }
        }
        float* cb = ctx + ((size_t)(b * LQ_ + l0)) * D_ + h * HD_;
#pragma unroll
        for (int i = 0; i < 4; i++) {
            float4 o = make_float4(acc[i][0], acc[i][1], acc[i][2], acc[i][3]);
            *(float4*)(cb + (size_t)(ty * 4 + i) * D_ + tx * 4) = o;
        }
    }
}

// ---------------------------------------------------------------------------
// Epilogue: two layer-norms of ffn row + sigmoid box from attn_output[:4]
// one block (256 threads) per row; row = 1024 floats = one float4 per thread.
// ---------------------------------------------------------------------------
#define OUT_TGT 8388608u    // B*LQ*D
#define OUT_BOX 16777216u   // 2*B*LQ*D

__global__ __launch_bounds__(256)
void ln_box_kernel(const float* __restrict__ ffn, const float* __restrict__ attn,
                   const float* __restrict__ g1, const float* __restrict__ be1,
                   const float* __restrict__ g2, const float* __restrict__ be2,
                   float* __restrict__ out)
{
    __shared__ float red[8];
    __shared__ float bcast;
    const int row = blockIdx.x;
    const int tid = threadIdx.x;
    const int lane = tid & 31, w = tid >> 5;

    float4 x = ((const float4*)(ffn + (size_t)row * D_))[tid];

    // mean
    float s = x.x + x.y + x.z + x.w;
#pragma unroll
    for (int o = 16; o; o >>= 1) s += __shfl_xor_sync(0xffffffffu, s, o);
    if (lane == 0) red[w] = s;
    __syncthreads();
    if (w == 0) {
        float t = (lane < 8) ? red[lane] : 0.f;
#pragma unroll
        for (int o = 4; o; o >>= 1) t += __shfl_xor_sync(0xffffffffu, t, o);
        if (lane == 0) bcast = t * (1.f / 1024.f);
    }
    __syncthreads();
    const float mean = bcast;
    __syncthreads();

    float dx = x.x - mean, dy = x.y - mean, dz = x.z - mean, dw = x.w - mean;
    float sq = dx * dx + dy * dy + dz * dz + dw * dw;
#pragma unroll
    for (int o = 16; o; o >>= 1) sq += __shfl_xor_sync(0xffffffffu, sq, o);
    if (lane == 0) red[w] = sq;
    __syncthreads();
    if (w == 0) {
        float t = (lane < 8) ? red[lane] : 0.f;
#pragma unroll
        for (int o = 4; o; o >>= 1) t += __shfl_xor_sync(0xffffffffu, t, o);
        if (lane == 0) bcast = rsqrtf(t * (1.f / 1024.f) + 1e-5f);
    }
    __syncthreads();
    const float inv = bcast;

    float4 G1 = ((const float4*)g1)[tid];
    float4 B1 = ((const float4*)be1)[tid];
    float4 G2 = ((const float4*)g2)[tid];
    float4 B2 = ((const float4*)be2)[tid];

    float4 o1, o2;
    o1.x = dx * inv * G1.x + B1.x;  o2.x = dx * inv * G2.x + B2.x;
    o1.y = dy * inv * G1.y + B1.y;  o2.y = dy * inv * G2.y + B2.y;
    o1.z = dz * inv * G1.z + B1.z;  o2.z = dz * inv * G2.z + B2.z;
    o1.w = dw * inv * G1.w + B1.w;  o2.w = dw * inv * G2.w + B2.w;

    ((float4*)out)[(size_t)row * 256 + tid]             = o1;
    ((float4*)(out + OUT_TGT))[(size_t)row * 256 + tid] = o2;

    if (tid == 0) {
        const float* a = attn + (size_t)row * D_;
        float xc = 1.f / (1.f + __expf(-a[0]));
        float yc = 1.f / (1.f + __expf(-a[1]));
        float ww = 1.f / (1.f + __expf(-a[2]));
        float hh = 1.f / (1.f + __expf(-a[3]));
        float4 box = make_float4(xc - ww * 0.5f, yc - hh * 0.5f,
                                 xc + ww * 0.5f, yc + hh * 0.5f);
        *(float4*)(out + OUT_BOX + (size_t)row * 4) = box;
    }
}

// ---------------------------------------------------------------------------
// Launch
// ---------------------------------------------------------------------------
extern "C" void kernel_launch(void* const* d_in, const int* in_sizes, int n_in,
                              void* d_out, int out_size)
{
    const float* memory = (const float*)d_in[0];   // [B,LQ,512]
    const float* gaze   = (const float*)d_in[1];   // [B,LQ,512]
    const float* text   = (const float*)d_in[2];   // [B,S,D]
    const float* w_in   = (const float*)d_in[3];   // [3D,D]
    const float* b_in   = (const float*)d_in[4];   // [3D]
    const float* w_o    = (const float*)d_in[5];   // [D,D]
    const float* b_o    = (const float*)d_in[6];   // [D]
    const float* w1     = (const float*)d_in[7];
    const float* b1     = (const float*)d_in[8];
    const float* w2     = (const float*)d_in[9];
    const float* b2     = (const float*)d_in[10];
    const float* g1     = (const float*)d_in[11];
    const float* be1    = (const float*)d_in[12];
    const float* g2     = (const float*)d_in[13];
    const float* be2    = (const float*)d_in[14];
    float* out = (float*)d_out;

    float *Q, *Kb, *Vb, *CTX, *ATT, *MID, *FFN;
    cudaGetSymbolAddress((void**)&Q,   g_q);
    cudaGetSymbolAddress((void**)&Kb,  g_k);
    cudaGetSymbolAddress((void**)&Vb,  g_v);
    cudaGetSymbolAddress((void**)&CTX, g_ctx);
    cudaGetSymbolAddress((void**)&ATT, g_att);
    cudaGetSymbolAddress((void**)&MID, g_mid);
    cudaGetSymbolAddress((void**)&FFN, g_ffn);

    cudaFuncSetAttribute(attn_kernel,
                         cudaFuncAttributeMaxDynamicSharedMemorySize,
                         ATT_SMEM_BYTES);

    dim3 blk(256);
    dim3 gQ(D_ / 128, MQ_ / 128);    // (8, 64)
    dim3 gKV(D_ / 128, MKV_ / 128);  // (8, 16)

    // Q projection: fused concat(memory, gaze) @ wq^T + bq
    sgemm_nt<<<gQ, blk>>>(MQ_, D_, D_,
                          memory, 512, gaze, 512, 512,
                          w_in, D_, b_in, Q, D_, 0);
    // K projection
    sgemm_nt<<<gKV, blk>>>(MKV_, D_, D_,
                           text, D_, text, D_, D_,
                           w_in + (size_t)D_ * D_, D_, b_in + D_, Kb, D_, 0);
    // V projection
    sgemm_nt<<<gKV, blk>>>(MKV_, D_, D_,
                           text, D_, text, D_, D_,
                           w_in + 2 * (size_t)D_ * D_, D_, b_in + 2 * D_, Vb, D_, 0);

    // attention
    dim3 gA(LQ_ / 64, H_, B_);       // (16, 16, 8)
    attn_kernel<<<gA, blk, ATT_SMEM_BYTES>>>(Q, Kb, Vb, CTX);

    // output projection
    sgemm_nt<<<gQ, blk>>>(MQ_, D_, D_,
                          CTX, D_, CTX, D_, D_,
                          w_o, D_, b_o, ATT, D_, 0);
    // FFN layer 1 (relu)
    sgemm_nt<<<gQ, blk>>>(MQ_, D_, D_,
                          ATT, D_, ATT, D_, D_,
                          w1, D_, b1, MID, D_, 1);
    // FFN layer 2
    sgemm_nt<<<gQ, blk>>>(MQ_, D_, D_,
                          MID, D_, MID, D_, D_,
                          w2, D_, b2, FFN, D_, 0);

    // layer norms + box proposal
    ln_box_kernel<<<MQ_, blk>>>(FFN, ATT, g1, be1, g2, be2, out);
}

// round 8
// speedup vs baseline: 1.0020x; 1.0020x over previous
#include <cuda_runtime.h>
#include <math.h>

// Problem constants
#define B_   8
#define LQ_  1024
#define S_   256
#define D_   1024
#define H_   16
#define HD_  64
#define MQ_  (B_*LQ_)   // 8192
#define MKV_ (B_*S_)    // 2048

// ---------------------------------------------------------------------------
// Scratch (static device globals — no allocation in kernel_launch)
// ---------------------------------------------------------------------------
__device__ float g_q  [MQ_  * D_];
__device__ float g_k  [MKV_ * D_];
__device__ float g_v  [MKV_ * D_];
__device__ float g_ctx[MQ_  * D_];
__device__ float g_att[MQ_  * D_];
__device__ float g_mid[MQ_  * D_];
__device__ float g_ffn[MQ_  * D_];

// ---------------------------------------------------------------------------
// SGEMM NT: C[M,N] = act(A[M,K] * B[N,K]^T + bias)
// A is split at column ksplit between A0 (lda0) and A1 (lda1) to fuse concat.
// BM=BN=128, BK=16, 256 threads, 8x8 microtile (2x2 raked 64-blocks).
// ---------------------------------------------------------------------------
__global__ __launch_bounds__(256, 2)
void sgemm_nt(int M, int N, int K,
              const float* __restrict__ A0, int lda0,
              const float* __restrict__ A1, int lda1, int ksplit,
              const float* __restrict__ Bm, int ldb,
              const float* __restrict__ bias,
              float* __restrict__ C, int ldc, int act)
{
    __shared__ float As[16 * 128];
    __shared__ float Bs[16 * 128];

    const int tid = threadIdx.x;
    const int tx  = tid & 15;   // col group
    const int ty  = tid >> 4;   // row group
    const int m0  = blockIdx.y * 128;
    const int n0  = blockIdx.x * 128;

    float acc[8][8];
#pragma unroll
    for (int i = 0; i < 8; i++)
#pragma unroll
        for (int j = 0; j < 8; j++) acc[i][j] = 0.f;

    for (int k0 = 0; k0 < K; k0 += 16) {
        // --- load A tile (128 rows x 16 k), transposed into As[k][row]
        const bool side0 = (k0 < ksplit);
#pragma unroll
        for (int it = 0; it < 2; it++) {
            int e   = tid + it * 256;
            int row = e >> 2;
            int c4  = e & 3;
            int gr  = m0 + row;
            const float* ap = side0 ? (A0 + (size_t)gr * lda0 + k0)
                                    : (A1 + (size_t)gr * lda1 + (k0 - ksplit));
            float4 v = *(const float4*)(ap + c4 * 4);
            As[(c4 * 4 + 0) * 128 + row] = v.x;
            As[(c4 * 4 + 1) * 128 + row] = v.y;
            As[(c4 * 4 + 2) * 128 + row] = v.z;
            As[(c4 * 4 + 3) * 128 + row] = v.w;
        }
        // --- load B tile (128 n-rows x 16 k), transposed into Bs[k][n]
#pragma unroll
        for (int it = 0; it < 2; it++) {
            int e   = tid + it * 256;
            int row = e >> 2;
            int c4  = e & 3;
            int gn  = n0 + row;
            float4 v = *(const float4*)(Bm + (size_t)gn * ldb + k0 + c4 * 4);
            Bs[(c4 * 4 + 0) * 128 + row] = v.x;
            Bs[(c4 * 4 + 1) * 128 + row] = v.y;
            Bs[(c4 * 4 + 2) * 128 + row] = v.z;
            Bs[(c4 * 4 + 3) * 128 + row] = v.w;
        }
        __syncthreads();

#pragma unroll
        for (int kk = 0; kk < 16; kk++) {
            float ra[8], rb[8];
#pragma unroll
            for (int i = 0; i < 4; i++) {
                ra[i]     = As[kk * 128 +       ty * 4 + i];
                ra[4 + i] = As[kk * 128 + 64 +  ty * 4 + i];
            }
            float4 b0 = *(const float4*)&Bs[kk * 128 +      tx * 4];
            float4 b1 = *(const float4*)&Bs[kk * 128 + 64 + tx * 4];
            rb[0] = b0.x; rb[1] = b0.y; rb[2] = b0.z; rb[3] = b0.w;
            rb[4] = b1.x; rb[5] = b1.y; rb[6] = b1.z; rb[7] = b1.w;
#pragma unroll
            for (int i = 0; i < 8; i++)
#pragma unroll
                for (int j = 0; j < 8; j++)
                    acc[i][j] = fmaf(ra[i], rb[j], acc[i][j]);
        }
        __syncthreads();
    }

    // --- epilogue: bias + optional relu, vectorized store
#pragma unroll
    for (int ri = 0; ri < 2; ri++) {
#pragma unroll
        for (int i = 0; i < 4; i++) {
            int gr = m0 + ri * 64 + ty * 4 + i;
#pragma unroll
            for (int rj = 0; rj < 2; rj++) {
                int gc = n0 + rj * 64 + tx * 4;
                float4 bv = *(const float4*)&bias[gc];
                float4 o;
                o.x = acc[ri * 4 + i][rj * 4 + 0] + bv.x;
                o.y = acc[ri * 4 + i][rj * 4 + 1] + bv.y;
                o.z = acc[ri * 4 + i][rj * 4 + 2] + bv.z;
                o.w = acc[ri * 4 + i][rj * 4 + 3] + bv.w;
                if (act == 1) {
                    o.x = fmaxf(o.x, 0.f); o.y = fmaxf(o.y, 0.f);
                    o.z = fmaxf(o.z, 0.f); o.w = fmaxf(o.w, 0.f);
                }
                *(float4*)&C[(size_t)gr * ldc + gc] = o;
            }
        }
    }
}

// ---------------------------------------------------------------------------
// Attention: per (b, h, 64-q-row tile).
//   P = softmax(Q K^T / 8), ctx = P V.  S=256 keys, HD=64, fully in smem.
// smem: QsT[64d][64r] | KsT[64d][256s] | Vs[256s][64d] | P[256s][65(r pad)]
// ---------------------------------------------------------------------------
#define ATT_SMEM_FLOATS (4096 + 16384 + 16384 + 16640)
#define ATT_SMEM_BYTES  (ATT_SMEM_FLOATS * 4)

__global__ __launch_bounds__(256, 1)
void attn_kernel(const float* __restrict__ q, const float* __restrict__ k,
                 const float* __restrict__ v, float* __restrict__ ctx)
{
    extern __shared__ float sm[];
    float* QsT = sm;               // [d][r]  64*64
    float* KsT = QsT + 4096;       // [d][s]  64*256
    float* Vs  = KsT + 16384;      // [s][d]  256*64
    float* P   = Vs  + 16384;      // [s][r]  256*65 (pad)

    const int tid = threadIdx.x;
    const int l0  = blockIdx.x * 64;
    const int h   = blockIdx.y;
    const int b   = blockIdx.z;

    const float* qb = q + ((size_t)(b * LQ_ + l0)) * D_ + h * HD_;
    const float* kb = k + ((size_t)(b * S_)) * D_ + h * HD_;
    const float* vb = v + ((size_t)(b * S_)) * D_ + h * HD_;

    // loads (float4, coalesced)
    for (int e = tid; e < 64 * 16; e += 256) {           // Q tile
        int r = e >> 4, d4 = e & 15;
        float4 vv = *(const float4*)(qb + (size_t)r * D_ + d4 * 4);
        QsT[(d4 * 4 + 0) * 64 + r] = vv.x;
        QsT[(d4 * 4 + 1) * 64 + r] = vv.y;
        QsT[(d4 * 4 + 2) * 64 + r] = vv.z;
        QsT[(d4 * 4 + 3) * 64 + r] = vv.w;
    }
    for (int e = tid; e < 256 * 16; e += 256) {          // K tile
        int s = e >> 4, d4 = e & 15;
        float4 vv = *(const float4*)(kb + (size_t)s * D_ + d4 * 4);
        KsT[(d4 * 4 + 0) * 256 + s] = vv.x;
        KsT[(d4 * 4 + 1) * 256 + s] = vv.y;
        KsT[(d4 * 4 + 2) * 256 + s] = vv.z;
        KsT[(d4 * 4 + 3) * 256 + s] = vv.w;
    }
    for (int e = tid; e < 256 * 16; e += 256) {          // V tile
        int s = e >> 4, d4 = e & 15;
        *(float4*)&Vs[s * 64 + d4 * 4] =
            *(const float4*)(vb + (size_t)s * D_ + d4 * 4);
    }
    __syncthreads();

    // phase A: P[s][r] = 0.125 * sum_d Q[r][d] K[s][d]   (64x256x64 GEMM)
    {
        const int tx = tid & 31;   // s groups
        const int ty = tid >> 5;   // r groups (0..7)
        float acc[8][8];
#pragma unroll
        for (int i = 0; i < 8; i++)
#pragma unroll
            for (int j = 0; j < 8; j++) acc[i][j] = 0.f;

#pragma unroll 4
        for (int d = 0; d < 64; d++) {
            float ra[8], rb[8];
#pragma unroll
            for (int i = 0; i < 4; i++) {
                ra[i]     = QsT[d * 64 +      ty * 4 + i];
                ra[4 + i] = QsT[d * 64 + 32 + ty * 4 + i];
            }
            float4 b0 = *(const float4*)&KsT[d * 256 +       tx * 4];
            float4 b1 = *(const float4*)&KsT[d * 256 + 128 + tx * 4];
            rb[0] = b0.x; rb[1] = b0.y; rb[2] = b0.z; rb[3] = b0.w;
            rb[4] = b1.x; rb[5] = b1.y; rb[6] = b1.z; rb[7] = b1.w;
#pragma unroll
            for (int i = 0; i < 8; i++)
#pragma unroll
                for (int j = 0; j < 8; j++)
                    acc[i][j] = fmaf(ra[i], rb[j], acc[i][j]);
        }
#pragma unroll
        for (int ri = 0; ri < 2; ri++)
#pragma unroll
            for (int i = 0; i < 4; i++)
#pragma unroll
                for (int rj = 0; rj < 2; rj++)
#pragma unroll
                    for (int j = 0; j < 4; j++) {
                        int r = ri * 32 + ty * 4 + i;
                        int s = rj * 128 + tx * 4 + j;
                        P[s * 65 + r] = acc[ri * 4 + i][rj * 4 + j] * 0.125f;
                    }
    }
    __syncthreads();

    // phase B: softmax over s for each of 64 rows (8 rows per warp)
    {
        const int lane = tid & 31, w = tid >> 5;
#pragma unroll
        for (int rr = 0; rr < 8; rr++) {
            int r = w * 8 + rr;
            float vals[8];
            float m = -1e30f;
#pragma unroll
            for (int qq = 0; qq < 8; qq++) {
                vals[qq] = P[(lane + qq * 32) * 65 + r];
                m = fmaxf(m, vals[qq]);
            }
#pragma unroll
            for (int off = 16; off; off >>= 1)
                m = fmaxf(m, __shfl_xor_sync(0xffffffffu, m, off));
            float sum = 0.f;
#pragma unroll
            for (int qq = 0; qq < 8; qq++) {
                vals[qq] = __expf(vals[qq] - m);
                sum += vals[qq];
            }
#pragma unroll
            for (int off = 16; off; off >>= 1)
                sum += __shfl_xor_sync(0xffffffffu, sum, off);
            float inv = 1.f / sum;
#pragma unroll
            for (int qq = 0; qq < 8; qq++)
                P[(lane + qq * 32) * 65 + r] = vals[qq] * inv;
        }
    }
    __syncthreads();

    // phase C: ctx[r][d] = sum_s P[s][r] V[s][d]   (64x64x256)
    {
        const int tx = tid & 15;   // d group
        const int ty = tid >> 4;   // r group
        float acc[4][4];
#pragma unroll
        for (int i = 0; i < 4; i++)
#pragma unroll
            for (int j = 0; j < 4; j++) acc[i][j] = 0.f;

#pragma unroll 8
        for (int s = 0; s < 256; s++) {
            float rp[4];
#pragma unroll
            for (int i = 0; i < 4; i++) rp[i] = P[s * 65 + ty * 4 + i];
            float4 vv = *(const float4*)&Vs[s * 64 + tx * 4];
#pragma unroll
            for (int i = 0; i < 4; i++) {
                acc[i][0] = fmaf(rp[i], vv.x, acc[i][0]);
                acc[i][1] = fmaf(rp[i], vv.y, acc[i][1]);
                acc[i][2] = fmaf(rp[i], vv.z, acc[i][2]);
                acc[i][3] = fmaf(rp[i], vv.w, acc[i][3]);
            }
        }
        float* cb = ctx + ((size_t)(b * LQ_ + l0)) * D_ + h * HD_;
#pragma unroll
        for (int i = 0; i < 4; i++) {
            float4 o = make_float4(acc[i][0], acc[i][1], acc[i][2], acc[i][3]);
            *(float4*)(cb + (size_t)(ty * 4 + i) * D_ + tx * 4) = o;
        }
    }
}

// ---------------------------------------------------------------------------
// Epilogue: two layer-norms of ffn row + sigmoid box from attn_output[:4]
// one block (256 threads) per row; row = 1024 floats = one float4 per thread.
// ---------------------------------------------------------------------------
#define OUT_TGT 8388608u    // B*LQ*D
#define OUT_BOX 16777216u   // 2*B*LQ*D

__global__ __launch_bounds__(256)
void ln_box_kernel(const float* __restrict__ ffn, const float* __restrict__ attn,
                   const float* __restrict__ g1, const float* __restrict__ be1,
                   const float* __restrict__ g2, const float* __restrict__ be2,
                   float* __restrict__ out)
{
    __shared__ float red[8];
    __shared__ float bcast;
    const int row = blockIdx.x;
    const int tid = threadIdx.x;
    const int lane = tid & 31, w = tid >> 5;

    float4 x = ((const float4*)(ffn + (size_t)row * D_))[tid];

    // mean
    float s = x.x + x.y + x.z + x.w;
#pragma unroll
    for (int o = 16; o; o >>= 1) s += __shfl_xor_sync(0xffffffffu, s, o);
    if (lane == 0) red[w] = s;
    __syncthreads();
    if (w == 0) {
        float t = (lane < 8) ? red[lane] : 0.f;
#pragma unroll
        for (int o = 4; o; o >>= 1) t += __shfl_xor_sync(0xffffffffu, t, o);
        if (lane == 0) bcast = t * (1.f / 1024.f);
    }
    __syncthreads();
    const float mean = bcast;
    __syncthreads();

    float dx = x.x - mean, dy = x.y - mean, dz = x.z - mean, dw = x.w - mean;
    float sq = dx * dx + dy * dy + dz * dz + dw * dw;
#pragma unroll
    for (int o = 16; o; o >>= 1) sq += __shfl_xor_sync(0xffffffffu, sq, o);
    if (lane == 0) red[w] = sq;
    __syncthreads();
    if (w == 0) {
        float t = (lane < 8) ? red[lane] : 0.f;
#pragma unroll
        for (int o = 4; o; o >>= 1) t += __shfl_xor_sync(0xffffffffu, t, o);
        if (lane == 0) bcast = rsqrtf(t * (1.f / 1024.f) + 1e-5f);
    }
    __syncthreads();
    const float inv = bcast;

    float4 G1 = ((const float4*)g1)[tid];
    float4 B1 = ((const float4*)be1)[tid];
    float4 G2 = ((const float4*)g2)[tid];
    float4 B2 = ((const float4*)be2)[tid];

    float4 o1, o2;
    o1.x = dx * inv * G1.x + B1.x;  o2.x = dx * inv * G2.x + B2.x;
    o1.y = dy * inv * G1.y + B1.y;  o2.y = dy * inv * G2.y + B2.y;
    o1.z = dz * inv * G1.z + B1.z;  o2.z = dz * inv * G2.z + B2.z;
    o1.w = dw * inv * G1.w + B1.w;  o2.w = dw * inv * G2.w + B2.w;

    ((float4*)out)[(size_t)row * 256 + tid]             = o1;
    ((float4*)(out + OUT_TGT))[(size_t)row * 256 + tid] = o2;

    if (tid == 0) {
        const float* a = attn + (size_t)row * D_;
        float xc = 1.f / (1.f + __expf(-a[0]));
        float yc = 1.f / (1.f + __expf(-a[1]));
        float ww = 1.f / (1.f + __expf(-a[2]));
        float hh = 1.f / (1.f + __expf(-a[3]));
        float4 box = make_float4(xc - ww * 0.5f, yc - hh * 0.5f,
                                 xc + ww * 0.5f, yc + hh * 0.5f);
        *(float4*)(out + OUT_BOX + (size_t)row * 4) = box;
    }
}

// ---------------------------------------------------------------------------
// Launch
// ---------------------------------------------------------------------------
extern "C" void kernel_launch(void* const* d_in, const int* in_sizes, int n_in,
                              void* d_out, int out_size)
{
    const float* memory = (const float*)d_in[0];   // [B,LQ,512]
    const float* gaze   = (const float*)d_in[1];   // [B,LQ,512]
    const float* text   = (const float*)d_in[2];   // [B,S,D]
    const float* w_in   = (const float*)d_in[3];   // [3D,D]
    const float* b_in   = (const float*)d_in[4];   // [3D]
    const float* w_o    = (const float*)d_in[5];   // [D,D]
    const float* b_o    = (const float*)d_in[6];   // [D]
    const float* w1     = (const float*)d_in[7];
    const float* b1     = (const float*)d_in[8];
    const float* w2     = (const float*)d_in[9];
    const float* b2     = (const float*)d_in[10];
    const float* g1     = (const float*)d_in[11];
    const float* be1    = (const float*)d_in[12];
    const float* g2     = (const float*)d_in[13];
    const float* be2    = (const float*)d_in[14];
    float* out = (float*)d_out;

    float *Q, *Kb, *Vb, *CTX, *ATT, *MID, *FFN;
    cudaGetSymbolAddress((void**)&Q,   g_q);
    cudaGetSymbolAddress((void**)&Kb,  g_k);
    cudaGetSymbolAddress((void**)&Vb,  g_v);
    cudaGetSymbolAddress((void**)&CTX, g_ctx);
    cudaGetSymbolAddress((void**)&ATT, g_att);
    cudaGetSymbolAddress((void**)&MID, g_mid);
    cudaGetSymbolAddress((void**)&FFN, g_ffn);

    cudaFuncSetAttribute(attn_kernel,
                         cudaFuncAttributeMaxDynamicSharedMemorySize,
                         ATT_SMEM_BYTES);

    dim3 blk(256);
    dim3 gQ(D_ / 128, MQ_ / 128);    // (8, 64)
    dim3 gKV(D_ / 128, MKV_ / 128);  // (8, 16)

    // Q projection: fused concat(memory, gaze) @ wq^T + bq
    sgemm_nt<<<gQ, blk>>>(MQ_, D_, D_,
                          memory, 512, gaze, 512, 512,
                          w_in, D_, b_in, Q, D_, 0);
    // K projection
    sgemm_nt<<<gKV, blk>>>(MKV_, D_, D_,
                           text, D_, text, D_, D_,
                           w_in + (size_t)D_ * D_, D_, b_in + D_, Kb, D_, 0);
    // V projection
    sgemm_nt<<<gKV, blk>>>(MKV_, D_, D_,
                           text, D_, text, D_, D_,
                           w_in + 2 * (size_t)D_ * D_, D_, b_in + 2 * D_, Vb, D_, 0);

    // attention
    dim3 gA(LQ_ / 64, H_, B_);       // (16, 16, 8)
    attn_kernel<<<gA, blk, ATT_SMEM_BYTES>>>(Q, Kb, Vb, CTX);

    // output projection
    sgemm_nt<<<gQ, blk>>>(MQ_, D_, D_,
                          CTX, D_, CTX, D_, D_,
                          w_o, D_, b_o, ATT, D_, 0);
    // FFN layer 1 (relu)
    sgemm_nt<<<gQ, blk>>>(MQ_, D_, D_,
                          ATT, D_, ATT, D_, D_,
                          w1, D_, b1, MID, D_, 1);
    // FFN layer 2
    sgemm_nt<<<gQ, blk>>>(MQ_, D_, D_,
                          MID, D_, MID, D_, D_,
                          w2, D_, b2, FFN, D_, 0);

    // layer norms + box proposal
    ln_box_kernel<<<MQ_, blk>>>(FFN, ATT, g1, be1, g2, be2, out);
}

// round 12
// speedup vs baseline: 1.8672x; 1.8635x over previous
#include <cuda_runtime.h>
#include <cuda_bf16.h>
#include <math.h>
#include <stdint.h>

// Problem constants
#define B_   8
#define LQ_  1024
#define S_   256
#define D_   1024
#define H_   16
#define HD_  64
#define MQ_  (B_*LQ_)   // 8192
#define MKV_ (B_*S_)    // 2048

// ---------------------------------------------------------------------------
// Scratch (static device globals — no allocation in kernel_launch)
// ---------------------------------------------------------------------------
__device__ float g_q  [MQ_  * D_];
__device__ float g_k  [MKV_ * D_];
__device__ float g_v  [MKV_ * D_];
__device__ float g_ctx[MQ_  * D_];
__device__ float g_att[MQ_  * D_];
__device__ float g_mid[MQ_  * D_];
__device__ float g_ffn[MQ_  * D_];

// ---------------------------------------------------------------------------
// Baseline-ISA tensor-core helpers (all legal on plain compute_103)
// ---------------------------------------------------------------------------
__device__ __forceinline__ uint32_t smem_u32(const void* p) {
    uint32_t a;
    asm("{ .reg .u64 t; cvta.to.shared.u64 t, %1; cvt.u32.u64 %0, t; }"
        : "=r"(a) : "l"(p));
    return a;
}

__device__ __forceinline__ void ldsm_x4(uint32_t* r, uint32_t addr) {
    asm volatile("ldmatrix.sync.aligned.m8n8.x4.shared.b16 {%0,%1,%2,%3}, [%4];"
                 : "=r"(r[0]), "=r"(r[1]), "=r"(r[2]), "=r"(r[3]) : "r"(addr));
}

__device__ __forceinline__ void mma16816(float* d, const uint32_t* a,
                                         uint32_t b0, uint32_t b1) {
    asm volatile(
        "mma.sync.aligned.m16n8k16.row.col.f32.bf16.bf16.f32 "
        "{%0,%1,%2,%3}, {%4,%5,%6,%7}, {%8,%9}, {%0,%1,%2,%3};"
        : "+f"(d[0]), "+f"(d[1]), "+f"(d[2]), "+f"(d[3])
        : "r"(a[0]), "r"(a[1]), "r"(a[2]), "r"(a[3]), "r"(b0), "r"(b1));
}

// ---------------------------------------------------------------------------
// HMMA GEMM NT, bf16x3 split: C = act(A[M,K] * B[N,K]^T + bias)
// A split at ksplit between A0/A1 (fused concat). Tile 128x128, K-chunk 32.
// SMEM stage: Ahi|Alo|Bhi|Blo, each 128 rows x 80B (32 bf16 + 16B pad).
// 2 stages, double buffered. 8 warps, each owns a 32x64 output sub-tile.
// ---------------------------------------------------------------------------
#define ROW_B   80                      // padded row stride (bytes)
#define TILE_B  (128 * ROW_B)           // 10240
#define STAGE_B (4 * TILE_B)            // 40960
#define GEMM_DSMEM (2 * STAGE_B)        // 81920

__global__ __launch_bounds__(256)
void gemm_tc(int M, int N, int K,
             const float* __restrict__ A0, int lda0,
             const float* __restrict__ A1, int lda1, int ksplit,
             const float* __restrict__ Bm, int ldb,
             const float* __restrict__ bias,
             float* __restrict__ C, int ldc, int act)
{
    extern __shared__ __align__(16) char smraw[];
    const uint32_t sbase = smem_u32(smraw);

    const int tid  = threadIdx.x;
    const int lane = tid & 31;
    const int w    = tid >> 5;
    const int m0   = blockIdx.y * 128;
    const int n0   = blockIdx.x * 128;
    const int mrow = (w & 3) * 32;      // warp row offset
    const int ncol = (w >> 2) * 64;     // warp col offset

    // accumulators: [mi 0..1][ni 0..7][4]
    float acc[2][8][4];
#pragma unroll
    for (int i = 0; i < 2; i++)
#pragma unroll
        for (int j = 0; j < 8; j++)
#pragma unroll
            for (int q = 0; q < 4; q++) acc[i][j][q] = 0.f;

    // loader lambda: convert one float4 -> hi/lo bf16x2 pairs, store swizzle-free
    auto cvt_store = [&](float4 v, char* hi, char* lo) {
        uint32_t h01, h23, l01, l23;
        asm("cvt.rn.bf16x2.f32 %0, %1, %2;" : "=r"(h01) : "f"(v.y), "f"(v.x));
        asm("cvt.rn.bf16x2.f32 %0, %1, %2;" : "=r"(h23) : "f"(v.w), "f"(v.z));
        float rx = v.x - __uint_as_float(h01 << 16);
        float ry = v.y - __uint_as_float(h01 & 0xffff0000u);
        float rz = v.z - __uint_as_float(h23 << 16);
        float rw = v.w - __uint_as_float(h23 & 0xffff0000u);
        asm("cvt.rn.bf16x2.f32 %0, %1, %2;" : "=r"(l01) : "f"(ry), "f"(rx));
        asm("cvt.rn.bf16x2.f32 %0, %1, %2;" : "=r"(l23) : "f"(rw), "f"(rz));
        *(uint2*)hi = make_uint2(h01, h23);
        *(uint2*)lo = make_uint2(l01, l23);
    };

    const int NC = K / 32;

    // ---- prologue: chunk 0 ------------------------------------------------
    {
        char* st = smraw;
        const int k0 = 0;
        const bool side0 = (k0 < ksplit);
#pragma unroll
        for (int it = 0; it < 4; it++) {            // A: 1024 float4
            int e = tid + it * 256;
            int row = e >> 3, c4 = e & 7;
            const float* ap = side0
                ? A0 + (size_t)(m0 + row) * lda0 + k0 + c4 * 4
                : A1 + (size_t)(m0 + row) * lda1 + (k0 - ksplit) + c4 * 4;
            float4 v = *(const float4*)ap;
            cvt_store(v, st + row * ROW_B + c4 * 8,
                         st + TILE_B + row * ROW_B + c4 * 8);
        }
#pragma unroll
        for (int it = 0; it < 4; it++) {            // B
            int e = tid + it * 256;
            int row = e >> 3, c4 = e & 7;
            float4 v = *(const float4*)(Bm + (size_t)(n0 + row) * ldb + k0 + c4 * 4);
            cvt_store(v, st + 2 * TILE_B + row * ROW_B + c4 * 8,
                         st + 3 * TILE_B + row * ROW_B + c4 * 8);
        }
    }
    __syncthreads();

    // ---- main loop --------------------------------------------------------
    for (int c = 0; c < NC; c++) {
        const int cur = c & 1;
        const uint32_t stg = sbase + cur * STAGE_B;

        // issue next-chunk global loads early (overlap with MMA below)
        float4 ra[4], rb[4];
        if (c + 1 < NC) {
            const int k0 = (c + 1) * 32;
            const bool side0 = (k0 < ksplit);
#pragma unroll
            for (int it = 0; it < 4; it++) {
                int e = tid + it * 256;
                int row = e >> 3, c4 = e & 7;
                const float* ap = side0
                    ? A0 + (size_t)(m0 + row) * lda0 + k0 + c4 * 4
                    : A1 + (size_t)(m0 + row) * lda1 + (k0 - ksplit) + c4 * 4;
                ra[it] = *(const float4*)ap;
                rb[it] = *(const float4*)(Bm + (size_t)((n0 + (e >> 3)) * (size_t)ldb)
                                          + k0 + c4 * 4);
            }
        }

        // MMA over this chunk: 2 k16 steps x 3 split terms
        const uint32_t aHb = stg;
        const uint32_t aLb = stg + TILE_B;
        const uint32_t bHb = stg + 2 * TILE_B;
        const uint32_t bLb = stg + 3 * TILE_B;
        const int rsel = lane & 7;
        const int radd = ((lane >> 3) & 1) * 8;
        const int cadd = ((lane >> 4) & 1) * 16;    // bytes (8 bf16)

#pragma unroll
        for (int ks = 0; ks < 2; ks++) {
            const int kb = ks * 32 + cadd;          // byte offset in row
            uint32_t aH[2][4], aL[2][4];
#pragma unroll
            for (int mi = 0; mi < 2; mi++) {
                uint32_t roff = (uint32_t)(mrow + mi * 16 + rsel + radd) * ROW_B + kb;
                ldsm_x4(aH[mi], aHb + roff);
                ldsm_x4(aL[mi], aLb + roff);
            }
#pragma unroll
            for (int j = 0; j < 4; j++) {           // n16 groups
                uint32_t bh[4], bl[4];
                uint32_t roff = (uint32_t)(ncol + j * 16 + rsel + radd) * ROW_B + kb;
                ldsm_x4(bh, bHb + roff);
                ldsm_x4(bl, bLb + roff);
#pragma unroll
                for (int mi = 0; mi < 2; mi++) {
                    mma16816(acc[mi][2*j],   aH[mi], bh[0], bh[2]);
                    mma16816(acc[mi][2*j+1], aH[mi], bh[1], bh[3]);
                    mma16816(acc[mi][2*j],   aH[mi], bl[0], bl[2]);
                    mma16816(acc[mi][2*j+1], aH[mi], bl[1], bl[3]);
                    mma16816(acc[mi][2*j],   aL[mi], bh[0], bh[2]);
                    mma16816(acc[mi][2*j+1], aL[mi], bh[1], bh[3]);
                }
            }
        }

        // convert + store next chunk into the other stage
        if (c + 1 < NC) {
            char* st = smraw + (cur ^ 1) * STAGE_B;
#pragma unroll
            for (int it = 0; it < 4; it++) {
                int e = tid + it * 256;
                int row = e >> 3, c4 = e & 7;
                cvt_store(ra[it], st + row * ROW_B + c4 * 8,
                                  st + TILE_B + row * ROW_B + c4 * 8);
                cvt_store(rb[it], st + 2 * TILE_B + row * ROW_B + c4 * 8,
                                  st + 3 * TILE_B + row * ROW_B + c4 * 8);
            }
        }
        __syncthreads();
    }

    // ---- epilogue: fp32 frags straight to C (float2 stores + bias) --------
    {
        const int r0 = lane >> 2;
        const int c0 = (lane & 3) * 2;
#pragma unroll
        for (int mi = 0; mi < 2; mi++) {
#pragma unroll
            for (int ni = 0; ni < 8; ni++) {
                int gr = m0 + mrow + mi * 16 + r0;
                int gc = n0 + ncol + ni * 8 + c0;
                float2 bv = *(const float2*)&bias[gc];
                float2 o0 = make_float2(acc[mi][ni][0] + bv.x,
                                        acc[mi][ni][1] + bv.y);
                float2 o1 = make_float2(acc[mi][ni][2] + bv.x,
                                        acc[mi][ni][3] + bv.y);
                if (act == 1) {
                    o0.x = fmaxf(o0.x, 0.f); o0.y = fmaxf(o0.y, 0.f);
                    o1.x = fmaxf(o1.x, 0.f); o1.y = fmaxf(o1.y, 0.f);
                }
                *(float2*)&C[(size_t)gr * ldc + gc]       = o0;
                *(float2*)&C[(size_t)(gr + 8) * ldc + gc] = o1;
            }
        }
    }
}

// ---------------------------------------------------------------------------
// Attention: per (b, h, 64-q-row tile).   (unchanged — 463us, next target)
// ---------------------------------------------------------------------------
#define ATT_SMEM_FLOATS (4096 + 16384 + 16384 + 16640)
#define ATT_SMEM_BYTES  (ATT_SMEM_FLOATS * 4)

__global__ __launch_bounds__(256, 1)
void attn_kernel(const float* __restrict__ q, const float* __restrict__ k,
                 const float* __restrict__ v, float* __restrict__ ctx)
{
    extern __shared__ float sm[];
    float* QsT = sm;               // [d][r]  64*64
    float* KsT = QsT + 4096;       // [d][s]  64*256
    float* Vs  = KsT + 16384;      // [s][d]  256*64
    float* P   = Vs  + 16384;      // [s][r]  256*65 (pad)

    const int tid = threadIdx.x;
    const int l0  = blockIdx.x * 64;
    const int h   = blockIdx.y;
    const int b   = blockIdx.z;

    const float* qb = q + ((size_t)(b * LQ_ + l0)) * D_ + h * HD_;
    const float* kb = k + ((size_t)(b * S_)) * D_ + h * HD_;
    const float* vb = v + ((size_t)(b * S_)) * D_ + h * HD_;

    for (int e = tid; e < 64 * 16; e += 256) {
        int r = e >> 4, d4 = e & 15;
        float4 vv = *(const float4*)(qb + (size_t)r * D_ + d4 * 4);
        QsT[(d4 * 4 + 0) * 64 + r] = vv.x;
        QsT[(d4 * 4 + 1) * 64 + r] = vv.y;
        QsT[(d4 * 4 + 2) * 64 + r] = vv.z;
        QsT[(d4 * 4 + 3) * 64 + r] = vv.w;
    }
    for (int e = tid; e < 256 * 16; e += 256) {
        int s = e >> 4, d4 = e & 15;
        float4 vv = *(const float4*)(kb + (size_t)s * D_ + d4 * 4);
        KsT[(d4 * 4 + 0) * 256 + s] = vv.x;
        KsT[(d4 * 4 + 1) * 256 + s] = vv.y;
        KsT[(d4 * 4 + 2) * 256 + s] = vv.z;
        KsT[(d4 * 4 + 3) * 256 + s] = vv.w;
    }
    for (int e = tid; e < 256 * 16; e += 256) {
        int s = e >> 4, d4 = e & 15;
        *(float4*)&Vs[s * 64 + d4 * 4] =
            *(const float4*)(vb + (size_t)s * D_ + d4 * 4);
    }
    __syncthreads();

    {
        const int tx = tid & 31;
        const int ty = tid >> 5;
        float acc[8][8];
#pragma unroll
        for (int i = 0; i < 8; i++)
#pragma unroll
            for (int j = 0; j < 8; j++) acc[i][j] = 0.f;

#pragma unroll 4
        for (int d = 0; d < 64; d++) {
            float ra[8], rb[8];
#pragma unroll
            for (int i = 0; i < 4; i++) {
                ra[i]     = QsT[d * 64 +      ty * 4 + i];
                ra[4 + i] = QsT[d * 64 + 32 + ty * 4 + i];
            }
            float4 b0 = *(const float4*)&KsT[d * 256 +       tx * 4];
            float4 b1 = *(const float4*)&KsT[d * 256 + 128 + tx * 4];
            rb[0] = b0.x; rb[1] = b0.y; rb[2] = b0.z; rb[3] = b0.w;
            rb[4] = b1.x; rb[5] = b1.y; rb[6] = b1.z; rb[7] = b1.w;
#pragma unroll
            for (int i = 0; i < 8; i++)
#pragma unroll
                for (int j = 0; j < 8; j++)
                    acc[i][j] = fmaf(ra[i], rb[j], acc[i][j]);
        }
#pragma unroll
        for (int ri = 0; ri < 2; ri++)
#pragma unroll
            for (int i = 0; i < 4; i++)
#pragma unroll
                for (int rj = 0; rj < 2; rj++)
#pragma unroll
                    for (int j = 0; j < 4; j++) {
                        int r = ri * 32 + ty * 4 + i;
                        int s = rj * 128 + tx * 4 + j;
                        P[s * 65 + r] = acc[ri * 4 + i][rj * 4 + j] * 0.125f;
                    }
    }
    __syncthreads();

    {
        const int lane = tid & 31, w = tid >> 5;
#pragma unroll
        for (int rr = 0; rr < 8; rr++) {
            int r = w * 8 + rr;
            float vals[8];
            float m = -1e30f;
#pragma unroll
            for (int qq = 0; qq < 8; qq++) {
                vals[qq] = P[(lane + qq * 32) * 65 + r];
                m = fmaxf(m, vals[qq]);
            }
#pragma unroll
            for (int off = 16; off; off >>= 1)
                m = fmaxf(m, __shfl_xor_sync(0xffffffffu, m, off));
            float sum = 0.f;
#pragma unroll
            for (int qq = 0; qq < 8; qq++) {
                vals[qq] = __expf(vals[qq] - m);
                sum += vals[qq];
            }
#pragma unroll
            for (int off = 16; off; off >>= 1)
                sum += __shfl_xor_sync(0xffffffffu, sum, off);
            float inv = 1.f / sum;
#pragma unroll
            for (int qq = 0; qq < 8; qq++)
                P[(lane + qq * 32) * 65 + r] = vals[qq] * inv;
        }
    }
    __syncthreads();

    {
        const int tx = tid & 15;
        const int ty = tid >> 4;
        float acc[4][4];
#pragma unroll
        for (int i = 0; i < 4; i++)
#pragma unroll
            for (int j = 0; j < 4; j++) acc[i][j] = 0.f;

#pragma unroll 8
        for (int s = 0; s < 256; s++) {
            float rp[4];
#pragma unroll
            for (int i = 0; i < 4; i++) rp[i] = P[s * 65 + ty * 4 + i];
            float4 vv = *(const float4*)&Vs[s * 64 + tx * 4];
#pragma unroll
            for (int i = 0; i < 4; i++) {
                acc[i][0] = fmaf(rp[i], vv.x, acc[i][0]);
                acc[i][1] = fmaf(rp[i], vv.y, acc[i][1]);
                acc[i][2] = fmaf(rp[i], vv.z, acc[i][2]);
                acc[i][3] = fmaf(rp[i], vv.w, acc[i][3]);
            }
        }
        float* cb = ctx + ((size_t)(b * LQ_ + l0)) * D_ + h * HD_;
#pragma unroll
        for (int i = 0; i < 4; i++) {
            float4 o = make_float4(acc[i][0], acc[i][1], acc[i][2], acc[i][3]);
            *(float4*)(cb + (size_t)(ty * 4 + i) * D_ + tx * 4) = o;
        }
    }
}

// ---------------------------------------------------------------------------
// Epilogue: two layer-norms + sigmoid box (unchanged)
// ---------------------------------------------------------------------------
#define OUT_TGT 8388608u
#define OUT_BOX 16777216u

__global__ __launch_bounds__(256)
void ln_box_kernel(const float* __restrict__ ffn, const float* __restrict__ attn,
                   const float* __restrict__ g1, const float* __restrict__ be1,
                   const float* __restrict__ g2, const float* __restrict__ be2,
                   float* __restrict__ out)
{
    __shared__ float red[8];
    __shared__ float bcast;
    const int row = blockIdx.x;
    const int tid = threadIdx.x;
    const int lane = tid & 31, w = tid >> 5;

    float4 x = ((const float4*)(ffn + (size_t)row * D_))[tid];

    float s = x.x + x.y + x.z + x.w;
#pragma unroll
    for (int o = 16; o; o >>= 1) s += __shfl_xor_sync(0xffffffffu, s, o);
    if (lane == 0) red[w] = s;
    __syncthreads();
    if (w == 0) {
        float t = (lane < 8) ? red[lane] : 0.f;
#pragma unroll
        for (int o = 4; o; o >>= 1) t += __shfl_xor_sync(0xffffffffu, t, o);
        if (lane == 0) bcast = t * (1.f / 1024.f);
    }
    __syncthreads();
    const float mean = bcast;
    __syncthreads();

    float dx = x.x - mean, dy = x.y - mean, dz = x.z - mean, dw = x.w - mean;
    float sq = dx * dx + dy * dy + dz * dz + dw * dw;
#pragma unroll
    for (int o = 16; o; o >>= 1) sq += __shfl_xor_sync(0xffffffffu, sq, o);
    if (lane == 0) red[w] = sq;
    __syncthreads();
    if (w == 0) {
        float t = (lane < 8) ? red[lane] : 0.f;
#pragma unroll
        for (int o = 4; o; o >>= 1) t += __shfl_xor_sync(0xffffffffu, t, o);
        if (lane == 0) bcast = rsqrtf(t * (1.f / 1024.f) + 1e-5f);
    }
    __syncthreads();
    const float inv = bcast;

    float4 G1 = ((const float4*)g1)[tid];
    float4 B1 = ((const float4*)be1)[tid];
    float4 G2 = ((const float4*)g2)[tid];
    float4 B2 = ((const float4*)be2)[tid];

    float4 o1, o2;
    o1.x = dx * inv * G1.x + B1.x;  o2.x = dx * inv * G2.x + B2.x;
    o1.y = dy * inv * G1.y + B1.y;  o2.y = dy * inv * G2.y + B2.y;
    o1.z = dz * inv * G1.z + B1.z;  o2.z = dz * inv * G2.z + B2.z;
    o1.w = dw * inv * G1.w + B1.w;  o2.w = dw * inv * G2.w + B2.w;

    ((float4*)out)[(size_t)row * 256 + tid]             = o1;
    ((float4*)(out + OUT_TGT))[(size_t)row * 256 + tid] = o2;

    if (tid == 0) {
        const float* a = attn + (size_t)row * D_;
        float xc = 1.f / (1.f + __expf(-a[0]));
        float yc = 1.f / (1.f + __expf(-a[1]));
        float ww = 1.f / (1.f + __expf(-a[2]));
        float hh = 1.f / (1.f + __expf(-a[3]));
        float4 box = make_float4(xc - ww * 0.5f, yc - hh * 0.5f,
                                 xc + ww * 0.5f, yc + hh * 0.5f);
        *(float4*)(out + OUT_BOX + (size_t)row * 4) = box;
    }
}

// ---------------------------------------------------------------------------
// Launch
// ---------------------------------------------------------------------------
extern "C" void kernel_launch(void* const* d_in, const int* in_sizes, int n_in,
                              void* d_out, int out_size)
{
    const float* memory = (const float*)d_in[0];
    const float* gaze   = (const float*)d_in[1];
    const float* text   = (const float*)d_in[2];
    const float* w_in   = (const float*)d_in[3];
    const float* b_in   = (const float*)d_in[4];
    const float* w_o    = (const float*)d_in[5];
    const float* b_o    = (const float*)d_in[6];
    const float* w1     = (const float*)d_in[7];
    const float* b1     = (const float*)d_in[8];
    const float* w2     = (const float*)d_in[9];
    const float* b2     = (const float*)d_in[10];
    const float* g1     = (const float*)d_in[11];
    const float* be1    = (const float*)d_in[12];
    const float* g2     = (const float*)d_in[13];
    const float* be2    = (const float*)d_in[14];
    float* out = (float*)d_out;

    float *Q, *Kb, *Vb, *CTX, *ATT, *MID, *FFN;
    cudaGetSymbolAddress((void**)&Q,   g_q);
    cudaGetSymbolAddress((void**)&Kb,  g_k);
    cudaGetSymbolAddress((void**)&Vb,  g_v);
    cudaGetSymbolAddress((void**)&CTX, g_ctx);
    cudaGetSymbolAddress((void**)&ATT, g_att);
    cudaGetSymbolAddress((void**)&MID, g_mid);
    cudaGetSymbolAddress((void**)&FFN, g_ffn);

    cudaFuncSetAttribute(attn_kernel,
                         cudaFuncAttributeMaxDynamicSharedMemorySize,
                         ATT_SMEM_BYTES);
    cudaFuncSetAttribute(gemm_tc,
                         cudaFuncAttributeMaxDynamicSharedMemorySize,
                         GEMM_DSMEM);

    dim3 blk(256);
    dim3 gQ(D_ / 128, MQ_ / 128);    // (8, 64)
    dim3 gKV(D_ / 128, MKV_ / 128);  // (8, 16)

    // Q projection: fused concat(memory, gaze) @ wq^T + bq
    gemm_tc<<<gQ, blk, GEMM_DSMEM>>>(MQ_, D_, D_,
                          memory, 512, gaze, 512, 512,
                          w_in, D_, b_in, Q, D_, 0);
    // K projection
    gemm_tc<<<gKV, blk, GEMM_DSMEM>>>(MKV_, D_, D_,
                           text, D_, text, D_, D_,
                           w_in + (size_t)D_ * D_, D_, b_in + D_, Kb, D_, 0);
    // V projection
    gemm_tc<<<gKV, blk, GEMM_DSMEM>>>(MKV_, D_, D_,
                           text, D_, text, D_, D_,
                           w_in + 2 * (size_t)D_ * D_, D_, b_in + 2 * D_, Vb, D_, 0);

    // attention
    dim3 gA(LQ_ / 64, H_, B_);
    attn_kernel<<<gA, blk, ATT_SMEM_BYTES>>>(Q, Kb, Vb, CTX);

    // output projection
    gemm_tc<<<gQ, blk, GEMM_DSMEM>>>(MQ_, D_, D_,
                          CTX, D_, CTX, D_, D_,
                          w_o, D_, b_o, ATT, D_, 0);
    // FFN layer 1 (relu)
    gemm_tc<<<gQ, blk, GEMM_DSMEM>>>(MQ_, D_, D_,
                          ATT, D_, ATT, D_, D_,
                          w1, D_, b1, MID, D_, 1);
    // FFN layer 2
    gemm_tc<<<gQ, blk, GEMM_DSMEM>>>(MQ_, D_, D_,
                          MID, D_, MID, D_, D_,
                          w2, D_, b2, FFN, D_, 0);

    // layer norms + box proposal
    ln_box_kernel<<<MQ_, blk>>>(FFN, ATT, g1, be1, g2, be2, out);
}

// round 13
// speedup vs baseline: 2.6507x; 1.4196x over previous
#include <cuda_runtime.h>
#include <cuda_bf16.h>
#include <math.h>
#include <stdint.h>

// Problem constants
#define B_   8
#define LQ_  1024
#define S_   256
#define D_   1024
#define H_   16
#define HD_  64
#define MQ_  (B_*LQ_)   // 8192
#define MKV_ (B_*S_)    // 2048

// ---------------------------------------------------------------------------
// Scratch (static device globals — no allocation in kernel_launch)
// ---------------------------------------------------------------------------
__device__ __nv_bfloat16 g_cAh[MQ_*D_],  g_cAl[MQ_*D_];    // concat(memory,gaze)
__device__ __nv_bfloat16 g_th [MKV_*D_], g_tl [MKV_*D_];   // text
__device__ __nv_bfloat16 g_wih[3*D_*D_], g_wil[3*D_*D_];   // w_in
__device__ __nv_bfloat16 g_woh[D_*D_],   g_wol[D_*D_];
__device__ __nv_bfloat16 g_w1h[D_*D_],   g_w1l[D_*D_];
__device__ __nv_bfloat16 g_w2h[D_*D_],   g_w2l[D_*D_];
__device__ __nv_bfloat16 g_qh [MQ_*D_],  g_ql [MQ_*D_];    // q (pre-scaled 1/8)
__device__ __nv_bfloat16 g_kh [MKV_*D_], g_kl [MKV_*D_];
__device__ __nv_bfloat16 g_vh [MKV_*D_], g_vl [MKV_*D_];
__device__ __nv_bfloat16 g_ch [MQ_*D_],  g_cl [MQ_*D_];    // ctx
__device__ __nv_bfloat16 g_ah [MQ_*D_],  g_al [MQ_*D_];    // attn_output
__device__ __nv_bfloat16 g_mh [MQ_*D_],  g_ml [MQ_*D_];    // relu mid
__device__ float g_att[MQ_*D_];                            // attn_output fp32
__device__ float g_ffn[MQ_*D_];                            // ffn fp32

// ---------------------------------------------------------------------------
// Baseline-ISA helpers (legal on plain compute_103)
// ---------------------------------------------------------------------------
__device__ __forceinline__ uint32_t smem_u32(const void* p) {
    uint32_t a;
    asm("{ .reg .u64 t; cvta.to.shared.u64 t, %1; cvt.u32.u64 %0, t; }"
        : "=r"(a) : "l"(p));
    return a;
}
__device__ __forceinline__ void ldsm_x4(uint32_t* r, uint32_t addr) {
    asm volatile("ldmatrix.sync.aligned.m8n8.x4.shared.b16 {%0,%1,%2,%3}, [%4];"
                 : "=r"(r[0]), "=r"(r[1]), "=r"(r[2]), "=r"(r[3]) : "r"(addr));
}
__device__ __forceinline__ void mma16816(float* d, const uint32_t* a,
                                         uint32_t b0, uint32_t b1) {
    asm volatile(
        "mma.sync.aligned.m16n8k16.row.col.f32.bf16.bf16.f32 "
        "{%0,%1,%2,%3}, {%4,%5,%6,%7}, {%8,%9}, {%0,%1,%2,%3};"
        : "+f"(d[0]), "+f"(d[1]), "+f"(d[2]), "+f"(d[3])
        : "r"(a[0]), "r"(a[1]), "r"(a[2]), "r"(a[3]), "r"(b0), "r"(b1));
}
__device__ __forceinline__ void cp16(uint32_t dst, const void* src) {
    asm volatile("cp.async.cg.shared.global [%0], [%1], 16;"
                 :: "r"(dst), "l"(src));
}
#define CP_COMMIT() asm volatile("cp.async.commit_group;" ::: "memory")
#define CP_WAIT0()  asm volatile("cp.async.wait_group 0;" ::: "memory")

// pack two fp32 into bf16x2 hi + residual-lo bf16x2 (lower half = first arg)
__device__ __forceinline__ void pack_hl(float x, float y,
                                        uint32_t& hi, uint32_t& lo) {
    asm("cvt.rn.bf16x2.f32 %0, %1, %2;" : "=r"(hi) : "f"(y), "f"(x));
    float rx = x - __uint_as_float(hi << 16);
    float ry = y - __uint_as_float(hi & 0xffff0000u);
    asm("cvt.rn.bf16x2.f32 %0, %1, %2;" : "=r"(lo) : "f"(ry), "f"(rx));
}

// ---------------------------------------------------------------------------
// One-time fp32 -> bf16 hi/lo split (grid: (rows*cols4+255)/256)
// ---------------------------------------------------------------------------
__global__ void cvt_split(const float* __restrict__ src, int sld,
                          __nv_bfloat16* __restrict__ hi,
                          __nv_bfloat16* __restrict__ lo,
                          int dld, int rows, int cols4)
{
    int idx = blockIdx.x * blockDim.x + threadIdx.x;
    if (idx >= rows * cols4) return;
    int row = idx / cols4, c = idx - row * cols4;
    float4 v = *(const float4*)(src + (size_t)row * sld + c * 4);
    uint32_t h01, h23, l01, l23;
    pack_hl(v.x, v.y, h01, l01);
    pack_hl(v.z, v.w, h23, l23);
    *(uint2*)(hi + (size_t)row * dld + c * 4) = make_uint2(h01, h23);
    *(uint2*)(lo + (size_t)row * dld + c * 4) = make_uint2(l01, l23);
}

// ---------------------------------------------------------------------------
// gemm_bf3: C = act(scale*((Ah+Al)(Bh+Bl)^T + bias)); A [M,K], B [N,K] bf16.
// Tile 128x128, K-chunk 64, cp.async double buffer, XOR-swizzled 128B rows.
// Outputs: optional fp32 Cf, optional bf16 hi/lo Ch/Cl.
// ---------------------------------------------------------------------------
#define G_TILE  16384
#define G_STAGE 65536
#define G_DSMEM 131072

__global__ __launch_bounds__(256, 1)
void gemm_bf3(int M, int N, int K,
              const __nv_bfloat16* __restrict__ Ah,
              const __nv_bfloat16* __restrict__ Al,
              const __nv_bfloat16* __restrict__ Bh,
              const __nv_bfloat16* __restrict__ Bl,
              const float* __restrict__ bias, float scale, int act,
              float* __restrict__ Cf,
              __nv_bfloat16* __restrict__ Ch, __nv_bfloat16* __restrict__ Cl,
              int ldc)
{
    extern __shared__ __align__(16) char smc[];
    const uint32_t sb = smem_u32(smc);
    const int tid = threadIdx.x, lane = tid & 31, w = tid >> 5;
    const int m0 = blockIdx.y * 128, n0 = blockIdx.x * 128;
    const int mrow = (w & 3) * 32, ncol = (w >> 2) * 64;

    float acc[2][8][4];
#pragma unroll
    for (int i = 0; i < 2; i++)
#pragma unroll
        for (int j = 0; j < 8; j++)
#pragma unroll
            for (int q = 0; q < 4; q++) acc[i][j][q] = 0.f;

    auto issue = [&](int c, int stage) {
        const int k0 = c * 64;
        const uint32_t st = sb + stage * G_STAGE;
#pragma unroll
        for (int it = 0; it < 4; it++) {
            int e = tid + it * 256;
            int r = e >> 3, cc = e & 7;
            uint32_t off = r * 128 + ((cc * 16) ^ ((r & 7) << 4));
            const size_t ga = (size_t)(m0 + r) * K + k0 + cc * 8;
            const size_t gb = (size_t)(n0 + r) * K + k0 + cc * 8;
            cp16(st + off,              Ah + ga);
            cp16(st + G_TILE + off,     Al + ga);
            cp16(st + 2 * G_TILE + off, Bh + gb);
            cp16(st + 3 * G_TILE + off, Bl + gb);
        }
    };

    const int NC = K / 64;
    issue(0, 0); CP_COMMIT();

    const int cadd = ((lane >> 4) & 1) * 16;
    for (int c = 0; c < NC; ++c) {
        CP_WAIT0();
        __syncthreads();
        if (c + 1 < NC) { issue(c + 1, (c + 1) & 1); CP_COMMIT(); }
        const uint32_t st = sb + (c & 1) * G_STAGE;
#pragma unroll
        for (int ks = 0; ks < 4; ks++) {
            uint32_t aH[2][4], aL[2][4];
#pragma unroll
            for (int mi = 0; mi < 2; mi++) {
                int rA = mrow + mi * 16 + (lane & 15);
                uint32_t off = rA * 128 + ((ks * 32 + cadd) ^ ((rA & 7) << 4));
                ldsm_x4(aH[mi], st + off);
                ldsm_x4(aL[mi], st + G_TILE + off);
            }
#pragma unroll
            for (int j = 0; j < 4; j++) {
                int rB = ncol + j * 16 + (lane & 15);
                uint32_t off = rB * 128 + ((ks * 32 + cadd) ^ ((rB & 7) << 4));
                uint32_t bh[4], bl[4];
                ldsm_x4(bh, st + 2 * G_TILE + off);
                ldsm_x4(bl, st + 3 * G_TILE + off);
#pragma unroll
                for (int mi = 0; mi < 2; mi++) {
                    mma16816(acc[mi][2*j],   aH[mi], bh[0], bh[2]);
                    mma16816(acc[mi][2*j+1], aH[mi], bh[1], bh[3]);
                    mma16816(acc[mi][2*j],   aH[mi], bl[0], bl[2]);
                    mma16816(acc[mi][2*j+1], aH[mi], bl[1], bl[3]);
                    mma16816(acc[mi][2*j],   aL[mi], bh[0], bh[2]);
                    mma16816(acc[mi][2*j+1], aL[mi], bh[1], bh[3]);
                }
            }
        }
        __syncthreads();
    }

    // epilogue: bias/relu/scale -> fp32 and/or bf16 hi/lo
    const int r0 = lane >> 2, c0 = (lane & 3) * 2;
#pragma unroll
    for (int mi = 0; mi < 2; mi++) {
#pragma unroll
        for (int ni = 0; ni < 8; ni++) {
            int gr = m0 + mrow + mi * 16 + r0;
            int gc = n0 + ncol + ni * 8 + c0;
            float b0v = bias[gc], b1v = bias[gc + 1];
            float v0 = acc[mi][ni][0] + b0v, v1 = acc[mi][ni][1] + b1v;
            float v2 = acc[mi][ni][2] + b0v, v3 = acc[mi][ni][3] + b1v;
            if (act) {
                v0 = fmaxf(v0, 0.f); v1 = fmaxf(v1, 0.f);
                v2 = fmaxf(v2, 0.f); v3 = fmaxf(v3, 0.f);
            }
            v0 *= scale; v1 *= scale; v2 *= scale; v3 *= scale;
            if (Cf) {
                *(float2*)&Cf[(size_t)gr * ldc + gc]       = make_float2(v0, v1);
                *(float2*)&Cf[(size_t)(gr + 8) * ldc + gc] = make_float2(v2, v3);
            }
            if (Ch) {
                uint32_t hh, ll;
                pack_hl(v0, v1, hh, ll);
                *(uint32_t*)&Ch[(size_t)gr * ldc + gc] = hh;
                *(uint32_t*)&Cl[(size_t)gr * ldc + gc] = ll;
                pack_hl(v2, v3, hh, ll);
                *(uint32_t*)&Ch[(size_t)(gr + 8) * ldc + gc] = hh;
                *(uint32_t*)&Cl[(size_t)(gr + 8) * ldc + gc] = ll;
            }
        }
    }
}

// ---------------------------------------------------------------------------
// HMMA flash attention. Block = 128 q-rows x (b,h); warp = 16 q-rows, all S
// via 4 chunks of 64 keys with online softmax in C-fragment layout.
// Q pre-scaled by 1/8 at projection. bf16x3 for QK and PV.
// smem: Qh|Ql[128x64] Kh|Kl[256x64] Vth|Vtl[64x256] (all bf16, XOR swizzle)
// ---------------------------------------------------------------------------
#define AQH 0
#define AQL 16384
#define AKH 32768
#define AKL 65536
#define AVH 98304
#define AVL 131072
#define ATT_DSMEM 163840

__global__ __launch_bounds__(256, 1)
void attn_tc(const __nv_bfloat16* __restrict__ qh, const __nv_bfloat16* __restrict__ ql,
             const __nv_bfloat16* __restrict__ kh, const __nv_bfloat16* __restrict__ kl,
             const __nv_bfloat16* __restrict__ vh, const __nv_bfloat16* __restrict__ vl,
             __nv_bfloat16* __restrict__ ch, __nv_bfloat16* __restrict__ cl)
{
    extern __shared__ __align__(16) char smc[];
    const uint32_t sb = smem_u32(smc);
    const int tid = threadIdx.x, lane = tid & 31, w = tid >> 5;
    const int bq = blockIdx.x * 128;
    const int h  = blockIdx.y, b = blockIdx.z;

    // ---- loads (bf16 direct copies; V transposed) -------------------------
    const size_t qbase = ((size_t)(b * LQ_ + bq)) * D_ + h * HD_;
    for (int e = tid; e < 1024; e += 256) {
        int r = e >> 3, c = e & 7;
        uint32_t off = r * 128 + ((c * 16) ^ ((r & 7) << 4));
        *(uint4*)(smc + AQH + off) = *(const uint4*)(qh + qbase + (size_t)r * D_ + c * 8);
        *(uint4*)(smc + AQL + off) = *(const uint4*)(ql + qbase + (size_t)r * D_ + c * 8);
    }
    const size_t kbase = ((size_t)(b * S_)) * D_ + h * HD_;
    for (int e = tid; e < 2048; e += 256) {
        int r = e >> 3, c = e & 7;
        uint32_t off = r * 128 + ((c * 16) ^ ((r & 7) << 4));
        *(uint4*)(smc + AKH + off) = *(const uint4*)(kh + kbase + (size_t)r * D_ + c * 8);
        *(uint4*)(smc + AKL + off) = *(const uint4*)(kl + kbase + (size_t)r * D_ + c * 8);
    }
    for (int e = tid; e < 2048; e += 256) {     // Vt[d][s], 512B rows
        int s = e >> 3, d8 = (e & 7) * 8;
        uint4 uh = *(const uint4*)(vh + kbase + (size_t)s * D_ + d8);
        uint4 ul = *(const uint4*)(vl + kbase + (size_t)s * D_ + d8);
        const __nv_bfloat16* ph = (const __nv_bfloat16*)&uh;
        const __nv_bfloat16* pl = (const __nv_bfloat16*)&ul;
#pragma unroll
        for (int t = 0; t < 8; t++) {
            int d = d8 + t;
            uint32_t off = d * 512 + ((s * 2) ^ ((d & 7) << 4));
            *(__nv_bfloat16*)(smc + AVH + off) = ph[t];
            *(__nv_bfloat16*)(smc + AVL + off) = pl[t];
        }
    }
    __syncthreads();

    // ---- per-warp flash loop ---------------------------------------------
    const int qr = w * 16;
    const int rA = qr + (lane & 15);
    const int cadd = ((lane >> 4) & 1) * 16;

    float O[8][4];
#pragma unroll
    for (int j = 0; j < 8; j++)
#pragma unroll
        for (int q = 0; q < 4; q++) O[j][q] = 0.f;
    float m0 = -1e30f, m1 = -1e30f, l0 = 0.f, l1 = 0.f;

    for (int t = 0; t < 4; ++t) {
        const int s0 = t * 64;
        float sc[8][4];
#pragma unroll
        for (int j = 0; j < 8; j++)
#pragma unroll
            for (int q = 0; q < 4; q++) sc[j][q] = 0.f;

        // scores = (Qh+Ql)(Kh+Kl)^T  (Q pre-scaled by 1/8)
#pragma unroll
        for (int ks = 0; ks < 4; ks++) {
            uint32_t qoff = rA * 128 + ((ks * 32 + cadd) ^ ((rA & 7) << 4));
            uint32_t aH[4], aL[4];
            ldsm_x4(aH, sb + AQH + qoff);
            ldsm_x4(aL, sb + AQL + qoff);
#pragma unroll
            for (int p = 0; p < 4; p++) {
                int rB = s0 + p * 16 + (lane & 15);
                uint32_t boff = rB * 128 + ((ks * 32 + cadd) ^ ((rB & 7) << 4));
                uint32_t bh[4], bl[4];
                ldsm_x4(bh, sb + AKH + boff);
                ldsm_x4(bl, sb + AKL + boff);
                mma16816(sc[2*p],   aH, bh[0], bh[2]);
                mma16816(sc[2*p+1], aH, bh[1], bh[3]);
                mma16816(sc[2*p],   aH, bl[0], bl[2]);
                mma16816(sc[2*p+1], aH, bl[1], bl[3]);
                mma16816(sc[2*p],   aL, bh[0], bh[2]);
                mma16816(sc[2*p+1], aL, bh[1], bh[3]);
            }
        }

        // online softmax (rows r0 = lane>>2 and r0+8; quad = lanes xor 1,2)
        float mx0 = -1e30f, mx1 = -1e30f;
#pragma unroll
        for (int j = 0; j < 8; j++) {
            mx0 = fmaxf(mx0, fmaxf(sc[j][0], sc[j][1]));
            mx1 = fmaxf(mx1, fmaxf(sc[j][2], sc[j][3]));
        }
        mx0 = fmaxf(mx0, __shfl_xor_sync(0xffffffffu, mx0, 1));
        mx0 = fmaxf(mx0, __shfl_xor_sync(0xffffffffu, mx0, 2));
        mx1 = fmaxf(mx1, __shfl_xor_sync(0xffffffffu, mx1, 1));
        mx1 = fmaxf(mx1, __shfl_xor_sync(0xffffffffu, mx1, 2));
        float mn0 = fmaxf(m0, mx0), mn1 = fmaxf(m1, mx1);
        float a0 = __expf(m0 - mn0), a1 = __expf(m1 - mn1);
        m0 = mn0; m1 = mn1;
        float ls0 = 0.f, ls1 = 0.f;
#pragma unroll
        for (int j = 0; j < 8; j++) {
            sc[j][0] = __expf(sc[j][0] - m0);
            sc[j][1] = __expf(sc[j][1] - m0);
            sc[j][2] = __expf(sc[j][2] - m1);
            sc[j][3] = __expf(sc[j][3] - m1);
            ls0 += sc[j][0] + sc[j][1];
            ls1 += sc[j][2] + sc[j][3];
        }
        ls0 += __shfl_xor_sync(0xffffffffu, ls0, 1);
        ls0 += __shfl_xor_sync(0xffffffffu, ls0, 2);
        ls1 += __shfl_xor_sync(0xffffffffu, ls1, 1);
        ls1 += __shfl_xor_sync(0xffffffffu, ls1, 2);
        l0 = l0 * a0 + ls0;
        l1 = l1 * a1 + ls1;
#pragma unroll
        for (int j = 0; j < 8; j++) {
            O[j][0] *= a0; O[j][1] *= a0;
            O[j][2] *= a1; O[j][3] *= a1;
        }

        // PV: O += (Ph+Pl)(Vth+Vtl)   (C-frag -> A-frag repack)
#pragma unroll
        for (int g = 0; g < 4; g++) {
            uint32_t aPh[4], aPl[4];
            pack_hl(sc[2*g][0],   sc[2*g][1],   aPh[0], aPl[0]);
            pack_hl(sc[2*g][2],   sc[2*g][3],   aPh[1], aPl[1]);
            pack_hl(sc[2*g+1][0], sc[2*g+1][1], aPh[2], aPl[2]);
            pack_hl(sc[2*g+1][2], sc[2*g+1][3], aPh[3], aPl[3]);
#pragma unroll
            for (int pd = 0; pd < 4; pd++) {
                int rV = pd * 16 + (lane & 15);
                uint32_t voff = rV * 512 +
                    (((s0 + g * 16) * 2 + cadd) ^ ((rV & 7) << 4));
                uint32_t bh[4], bl[4];
                ldsm_x4(bh, sb + AVH + voff);
                ldsm_x4(bl, sb + AVL + voff);
                mma16816(O[2*pd],   aPh, bh[0], bh[2]);
                mma16816(O[2*pd+1], aPh, bh[1], bh[3]);
                mma16816(O[2*pd],   aPh, bl[0], bl[2]);
                mma16816(O[2*pd+1], aPh, bl[1], bl[3]);
                mma16816(O[2*pd],   aPl, bh[0], bh[2]);
                mma16816(O[2*pd+1], aPl, bh[1], bh[3]);
            }
        }
    }

    // ---- epilogue: O/l -> ctx bf16 hi/lo ---------------------------------
    const float i0 = 1.f / l0, i1 = 1.f / l1;
    const size_t gr0 = (size_t)(b * LQ_ + bq + qr + (lane >> 2));
    const size_t gr1 = gr0 + 8;
#pragma unroll
    for (int j = 0; j < 8; j++) {
        int gc = h * HD_ + j * 8 + (lane & 3) * 2;
        uint32_t hh, ll;
        pack_hl(O[j][0] * i0, O[j][1] * i0, hh, ll);
        *(uint32_t*)&ch[gr0 * D_ + gc] = hh;
        *(uint32_t*)&cl[gr0 * D_ + gc] = ll;
        pack_hl(O[j][2] * i1, O[j][3] * i1, hh, ll);
        *(uint32_t*)&ch[gr1 * D_ + gc] = hh;
        *(uint32_t*)&cl[gr1 * D_ + gc] = ll;
    }
}

// ---------------------------------------------------------------------------
// Epilogue: two layer-norms + sigmoid box (unchanged)
// ---------------------------------------------------------------------------
#define OUT_TGT 8388608u
#define OUT_BOX 16777216u

__global__ __launch_bounds__(256)
void ln_box_kernel(const float* __restrict__ ffn, const float* __restrict__ attn,
                   const float* __restrict__ g1, const float* __restrict__ be1,
                   const float* __restrict__ g2, const float* __restrict__ be2,
                   float* __restrict__ out)
{
    __shared__ float red[8];
    __shared__ float bcast;
    const int row = blockIdx.x;
    const int tid = threadIdx.x;
    const int lane = tid & 31, w = tid >> 5;

    float4 x = ((const float4*)(ffn + (size_t)row * D_))[tid];

    float s = x.x + x.y + x.z + x.w;
#pragma unroll
    for (int o = 16; o; o >>= 1) s += __shfl_xor_sync(0xffffffffu, s, o);
    if (lane == 0) red[w] = s;
    __syncthreads();
    if (w == 0) {
        float t = (lane < 8) ? red[lane] : 0.f;
#pragma unroll
        for (int o = 4; o; o >>= 1) t += __shfl_xor_sync(0xffffffffu, t, o);
        if (lane == 0) bcast = t * (1.f / 1024.f);
    }
    __syncthreads();
    const float mean = bcast;
    __syncthreads();

    float dx = x.x - mean, dy = x.y - mean, dz = x.z - mean, dw = x.w - mean;
    float sq = dx * dx + dy * dy + dz * dz + dw * dw;
#pragma unroll
    for (int o = 16; o; o >>= 1) sq += __shfl_xor_sync(0xffffffffu, sq, o);
    if (lane == 0) red[w] = sq;
    __syncthreads();
    if (w == 0) {
        float t = (lane < 8) ? red[lane] : 0.f;
#pragma unroll
        for (int o = 4; o; o >>= 1) t += __shfl_xor_sync(0xffffffffu, t, o);
        if (lane == 0) bcast = rsqrtf(t * (1.f / 1024.f) + 1e-5f);
    }
    __syncthreads();
    const float inv = bcast;

    float4 G1 = ((const float4*)g1)[tid];
    float4 B1 = ((const float4*)be1)[tid];
    float4 G2 = ((const float4*)g2)[tid];
    float4 B2 = ((const float4*)be2)[tid];

    float4 o1, o2;
    o1.x = dx * inv * G1.x + B1.x;  o2.x = dx * inv * G2.x + B2.x;
    o1.y = dy * inv * G1.y + B1.y;  o2.y = dy * inv * G2.y + B2.y;
    o1.z = dz * inv * G1.z + B1.z;  o2.z = dz * inv * G2.z + B2.z;
    o1.w = dw * inv * G1.w + B1.w;  o2.w = dw * inv * G2.w + B2.w;

    ((float4*)out)[(size_t)row * 256 + tid]             = o1;
    ((float4*)(out + OUT_TGT))[(size_t)row * 256 + tid] = o2;

    if (tid == 0) {
        const float* a = attn + (size_t)row * D_;
        float xc = 1.f / (1.f + __expf(-a[0]));
        float yc = 1.f / (1.f + __expf(-a[1]));
        float ww = 1.f / (1.f + __expf(-a[2]));
        float hh = 1.f / (1.f + __expf(-a[3]));
        float4 box = make_float4(xc - ww * 0.5f, yc - hh * 0.5f,
                                 xc + ww * 0.5f, yc + hh * 0.5f);
        *(float4*)(out + OUT_BOX + (size_t)row * 4) = box;
    }
}

// ---------------------------------------------------------------------------
// Launch
// ---------------------------------------------------------------------------
extern "C" void kernel_launch(void* const* d_in, const int* in_sizes, int n_in,
                              void* d_out, int out_size)
{
    const float* memory = (const float*)d_in[0];
    const float* gaze   = (const float*)d_in[1];
    const float* text   = (const float*)d_in[2];
    const float* w_in   = (const float*)d_in[3];
    const float* b_in   = (const float*)d_in[4];
    const float* w_o    = (const float*)d_in[5];
    const float* b_o    = (const float*)d_in[6];
    const float* w1     = (const float*)d_in[7];
    const float* b1     = (const float*)d_in[8];
    const float* w2     = (const float*)d_in[9];
    const float* b2     = (const float*)d_in[10];
    const float* g1     = (const float*)d_in[11];
    const float* be1    = (const float*)d_in[12];
    const float* g2     = (const float*)d_in[13];
    const float* be2    = (const float*)d_in[14];
    float* out = (float*)d_out;

    __nv_bfloat16 *cAh,*cAl,*th,*tl,*wih,*wil,*woh,*wol,*w1h,*w1l,*w2h,*w2l;
    __nv_bfloat16 *qh,*ql,*kh,*kl,*vh,*vl,*chb,*clb,*ah,*al,*mh,*ml;
    float *ATT,*FFN;
    cudaGetSymbolAddress((void**)&cAh, g_cAh); cudaGetSymbolAddress((void**)&cAl, g_cAl);
    cudaGetSymbolAddress((void**)&th,  g_th);  cudaGetSymbolAddress((void**)&tl,  g_tl);
    cudaGetSymbolAddress((void**)&wih, g_wih); cudaGetSymbolAddress((void**)&wil, g_wil);
    cudaGetSymbolAddress((void**)&woh, g_woh); cudaGetSymbolAddress((void**)&wol, g_wol);
    cudaGetSymbolAddress((void**)&w1h, g_w1h); cudaGetSymbolAddress((void**)&w1l, g_w1l);
    cudaGetSymbolAddress((void**)&w2h, g_w2h); cudaGetSymbolAddress((void**)&w2l, g_w2l);
    cudaGetSymbolAddress((void**)&qh,  g_qh);  cudaGetSymbolAddress((void**)&ql,  g_ql);
    cudaGetSymbolAddress((void**)&kh,  g_kh);  cudaGetSymbolAddress((void**)&kl,  g_kl);
    cudaGetSymbolAddress((void**)&vh,  g_vh);  cudaGetSymbolAddress((void**)&vl,  g_vl);
    cudaGetSymbolAddress((void**)&chb, g_ch);  cudaGetSymbolAddress((void**)&clb, g_cl);
    cudaGetSymbolAddress((void**)&ah,  g_ah);  cudaGetSymbolAddress((void**)&al,  g_al);
    cudaGetSymbolAddress((void**)&mh,  g_mh);  cudaGetSymbolAddress((void**)&ml,  g_ml);
    cudaGetSymbolAddress((void**)&ATT, g_att); cudaGetSymbolAddress((void**)&FFN, g_ffn);

    cudaFuncSetAttribute(gemm_bf3,
                         cudaFuncAttributeMaxDynamicSharedMemorySize, G_DSMEM);
    cudaFuncSetAttribute(attn_tc,
                         cudaFuncAttributeMaxDynamicSharedMemorySize, ATT_DSMEM);

    dim3 blk(256);

    // ---- one-time input/weight splits ----
    {
        int n1 = MQ_ * 128;          // memory / gaze: 8192 x 512 (cols4=128)
        cvt_split<<<(n1+255)/256, blk>>>(memory, 512, cAh,       cAl,       1024, MQ_, 128);
        cvt_split<<<(n1+255)/256, blk>>>(gaze,   512, cAh + 512, cAl + 512, 1024, MQ_, 128);
        int n2 = MKV_ * 256;         // text: 2048 x 1024
        cvt_split<<<(n2+255)/256, blk>>>(text, 1024, th, tl, 1024, MKV_, 256);
        int n3 = 3 * D_ * 256;       // w_in: 3072 x 1024
        cvt_split<<<(n3+255)/256, blk>>>(w_in, 1024, wih, wil, 1024, 3 * D_, 256);
        int n4 = D_ * 256;           // 1024 x 1024
        cvt_split<<<(n4+255)/256, blk>>>(w_o, 1024, woh, wol, 1024, D_, 256);
        cvt_split<<<(n4+255)/256, blk>>>(w1,  1024, w1h, w1l, 1024, D_, 256);
        cvt_split<<<(n4+255)/256, blk>>>(w2,  1024, w2h, w2l, 1024, D_, 256);
    }

    dim3 gQ(D_ / 128, MQ_ / 128);    // (8, 64)
    dim3 gKV(D_ / 128, MKV_ / 128);  // (8, 16)

    // Q projection (scale 1/8 folded in), bf16 out only
    gemm_bf3<<<gQ, blk, G_DSMEM>>>(MQ_, D_, D_, cAh, cAl, wih, wil,
                                   b_in, 0.125f, 0, nullptr, qh, ql, D_);
    // K projection
    gemm_bf3<<<gKV, blk, G_DSMEM>>>(MKV_, D_, D_, th, tl,
                                    wih + (size_t)D_ * D_, wil + (size_t)D_ * D_,
                                    b_in + D_, 1.f, 0, nullptr, kh, kl, D_);
    // V projection
    gemm_bf3<<<gKV, blk, G_DSMEM>>>(MKV_, D_, D_, th, tl,
                                    wih + 2*(size_t)D_*D_, wil + 2*(size_t)D_*D_,
                                    b_in + 2*D_, 1.f, 0, nullptr, vh, vl, D_);
    // attention -> ctx bf16 hi/lo
    dim3 gA(LQ_ / 128, H_, B_);      // (8, 16, 8)
    attn_tc<<<gA, blk, ATT_DSMEM>>>(qh, ql, kh, kl, vh, vl, chb, clb);
    // output projection -> ATT fp32 + bf16
    gemm_bf3<<<gQ, blk, G_DSMEM>>>(MQ_, D_, D_, chb, clb, woh, wol,
                                   b_o, 1.f, 0, ATT, ah, al, D_);
    // FFN1 (relu) -> bf16 only
    gemm_bf3<<<gQ, blk, G_DSMEM>>>(MQ_, D_, D_, ah, al, w1h, w1l,
                                   b1, 1.f, 1, nullptr, mh, ml, D_);
    // FFN2 -> fp32 only
    gemm_bf3<<<gQ, blk, G_DSMEM>>>(MQ_, D_, D_, mh, ml, w2h, w2l,
                                   b2, 1.f, 0, FFN, nullptr, nullptr, D_);

    // layer norms + box proposal
    ln_box_kernel<<<MQ_, blk>>>(FFN, ATT, g1, be1, g2, be2, out);
}